// round 2
// baseline (speedup 1.0000x reference)
#include <cuda_runtime.h>
#include <cstdint>
#include <cstddef>

#define BB 4
#define NN 4096
#define CC 64
#define KK 16
#define SS 2
#define SEG (NN/SS)      // 2048 db points per segment
#define QB 256           // queries per knn block
#define MB 128           // merge block size
#define WPB 8            // warps per mlp block
#define TPB (WPB*32)

// scratch (static device globals: no allocation allowed)
__device__ float g_cand_d[BB*NN*SS*KK];
__device__ int   g_cand_i[BB*NN*SS*KK];
__device__ int   g_knn[BB*NN*KK];

// ---- packed f32x2 helpers (FFMA2: only reachable via PTX fma.rn.f32x2) ----
__device__ __forceinline__ unsigned long long pack2(float lo, float hi){
  unsigned long long v;
  asm("mov.b64 %0, {%1,%2};" : "=l"(v) : "f"(lo), "f"(hi));
  return v;
}
__device__ __forceinline__ void unpack2(unsigned long long v, float &lo, float &hi){
  asm("mov.b64 {%0,%1}, %2;" : "=f"(lo), "=f"(hi) : "l"(v));
}
__device__ __forceinline__ unsigned long long ffma2(unsigned long long a,
                                                    unsigned long long b,
                                                    unsigned long long c){
  unsigned long long d;
  asm("fma.rn.f32x2 %0, %1, %2, %3;" : "=l"(d) : "l"(a), "l"(b), "l"(c));
  return d;
}

// ============================================================================
// Kernel 1: per-segment top-16 (register-resident, replace-by-value scheme)
// grid (NN/QB, SS, BB), block QB. Each thread owns one query, scans one
// 2048-point segment held in shared memory (SoA, broadcast reads).
// ============================================================================
__global__ __launch_bounds__(QB) void knn_partial(const float* __restrict__ xyz){
  __shared__ float sx[SEG], sy[SEG], sz[SEG];
  const int b = blockIdx.z, s = blockIdx.y;
  const float* base = xyz + (size_t)b * NN * 3;
  const int jg0 = s * SEG;
  for (int i = threadIdx.x; i < SEG; i += QB){
    int j = jg0 + i;
    sx[i] = base[j*3+0]; sy[i] = base[j*3+1]; sz[i] = base[j*3+2];
  }
  __syncthreads();

  const int q = blockIdx.x * QB + threadIdx.x;
  const float qx = base[q*3+0], qy = base[q*3+1], qz = base[q*3+2];

  // distinct huge sentinels so "replace entry equal to worst" hits exactly one
  float bd[KK]; int bi[KK];
  #pragma unroll
  for (int i = 0; i < KK; i++){
    bd[i] = __uint_as_float(0x7F000000u - (unsigned)i);
    bi[i] = 0;
  }
  float worst = __uint_as_float(0x7F000000u);

  #pragma unroll 4
  for (int j = 0; j < SEG; j++){
    float dx = qx - sx[j], dy = qy - sy[j], dz = qz - sz[j];
    float d = dx*dx;
    d = fmaf(dy, dy, d);
    d = fmaf(dz, dz, d);
    int jg = jg0 + j;
    if (d < worst && jg != q){
      #pragma unroll
      for (int i = 0; i < KK; i++){
        if (bd[i] == worst){ bd[i] = d; bi[i] = jg; }
      }
      // recompute worst via fmax tree (parallel, depth 4)
      float t0 = fmaxf(bd[0],  bd[1]),  t1 = fmaxf(bd[2],  bd[3]);
      float t2 = fmaxf(bd[4],  bd[5]),  t3 = fmaxf(bd[6],  bd[7]);
      float t4 = fmaxf(bd[8],  bd[9]),  t5 = fmaxf(bd[10], bd[11]);
      float t6 = fmaxf(bd[12], bd[13]), t7 = fmaxf(bd[14], bd[15]);
      t0 = fmaxf(t0, t1); t2 = fmaxf(t2, t3);
      t4 = fmaxf(t4, t5); t6 = fmaxf(t6, t7);
      worst = fmaxf(fmaxf(t0, t2), fmaxf(t4, t6));
    }
  }

  size_t o = (((size_t)b * NN + q) * SS + s) * KK;
  #pragma unroll
  for (int i = 0; i < KK; i++){ g_cand_d[o+i] = bd[i]; g_cand_i[o+i] = bi[i]; }
}

// ============================================================================
// Kernel 2: merge SS*16 candidates per query -> final 16 (unordered is fine:
// downstream is max-pool; ascending scan keeps lower index on exact ties,
// matching jax top_k tie-breaking)
// ============================================================================
__global__ __launch_bounds__(MB) void knn_merge(){
  __shared__ float sd[MB][SS*KK + 1];   // +1 pad kills bank conflicts
  __shared__ int   si[MB][SS*KK + 1];
  const int t = threadIdx.x;
  const int g = blockIdx.x * MB + t;    // global point id (b*NN+n)
  size_t o = (size_t)g * SS * KK;
  #pragma unroll
  for (int i = 0; i < SS*KK; i++){ sd[t][i] = g_cand_d[o+i]; si[t][i] = g_cand_i[o+i]; }

  const int outbase = g * KK;
  for (int r = 0; r < KK; r++){
    float best = 3.0e38f; int bp = 0;
    #pragma unroll
    for (int i = 0; i < SS*KK; i++){
      float v = sd[t][i];
      if (v < best){ best = v; bp = i; }
    }
    g_knn[outbase + r] = si[t][bp];
    sd[t][bp] = 3.2e38f;   // mark used
  }
}

// ============================================================================
// Kernel 3: fused rel-coords + 3-layer MLP + neighbor max-pool.
// One warp per point. Lane l owns output channels l and l+32.
// h tiles in shared as [c][nb] (16 floats/row) so neighbor pairs load as
// broadcast ld.shared.v2.b64 feeding packed fma.rn.f32x2 accumulators.
// ============================================================================
__global__ __launch_bounds__(TPB) void mlp_kernel(
    const float* __restrict__ xyz,
    const float* __restrict__ w1,
    const float* __restrict__ w2,
    const float* __restrict__ w3,
    float* __restrict__ out)
{
  extern __shared__ float sm[];
  float* w1s = sm;             // 192
  float* w2T = sm + 192;       // 4096  (w2T[c_in*64 + c_out])
  float* w3T = w2T + 4096;     // 4096
  float* hb  = w3T + 4096;     // WPB * 2048

  const int tid = threadIdx.x, wid = tid >> 5, lane = tid & 31;

  for (int t = tid; t < 192; t += TPB) w1s[t] = w1[t];
  for (int t = tid; t < 4096; t += TPB){
    int o = t >> 6, c = t & 63;
    w2T[c*64 + o] = w2[t];
    w3T[c*64 + o] = w3[t];
  }
  __syncthreads();

  const int point = blockIdx.x * WPB + wid;       // 0..BB*NN-1
  const int b = point >> 12;
  const int n = point & (NN - 1);
  const float* base = xyz + (size_t)b * NN * 3;

  float* h1 = hb + wid * 2048;
  float* h2 = h1 + 1024;

  const float cx = base[n*3+0], cy = base[n*3+1], cz = base[n*3+2];

  // stage relative coords in h2[0..47] (free until layer-2 writes)
  if (lane < KK){
    int ng = g_knn[point*KK + lane];
    h2[lane]      = base[ng*3+0] - cx;
    h2[16 + lane] = base[ng*3+1] - cy;
    h2[32 + lane] = base[ng*3+2] - cz;
  }
  __syncwarp();

  // ---- layer 1: h1[c][nb] = relu(w1[c] . rel[nb]) ----
  {
    const int c0 = lane, c1 = lane + 32;
    const float a0 = w1s[c0*3], b0 = w1s[c0*3+1], g0 = w1s[c0*3+2];
    const float a1 = w1s[c1*3], b1 = w1s[c1*3+1], g1 = w1s[c1*3+2];
    #pragma unroll
    for (int nb = 0; nb < KK; nb += 4){
      float o0[4], o1[4];
      #pragma unroll
      for (int u = 0; u < 4; u++){
        float rx = h2[nb+u], ry = h2[16+nb+u], rz = h2[32+nb+u];
        o0[u] = fmaxf(fmaf(a0, rx, fmaf(b0, ry, g0*rz)), 0.f);
        o1[u] = fmaxf(fmaf(a1, rx, fmaf(b1, ry, g1*rz)), 0.f);
      }
      *(float4*)(h1 + c0*16 + nb) = make_float4(o0[0], o0[1], o0[2], o0[3]);
      *(float4*)(h1 + c1*16 + nb) = make_float4(o1[0], o1[1], o1[2], o1[3]);
    }
  }
  __syncwarp();

  unsigned long long acc[16];

  // ---- layer 2: h2 = relu(W2 @ h1) ----
  #pragma unroll
  for (int p = 0; p < 16; p++) acc[p] = 0ull;
  #pragma unroll 2
  for (int j = 0; j < CC; j++){
    float wva = w2T[j*64 + lane];
    float wvb = w2T[j*64 + 32 + lane];
    unsigned long long wa = pack2(wva, wva);
    unsigned long long wb = pack2(wvb, wvb);
    const ulonglong2* hp = reinterpret_cast<const ulonglong2*>(h1 + j*16);
    #pragma unroll
    for (int p = 0; p < 4; p++){
      ulonglong2 hv = hp[p];
      acc[2*p]       = ffma2(wa, hv.x, acc[2*p]);
      acc[2*p+1]     = ffma2(wa, hv.y, acc[2*p+1]);
      acc[8 + 2*p]   = ffma2(wb, hv.x, acc[8 + 2*p]);
      acc[8 + 2*p+1] = ffma2(wb, hv.y, acc[8 + 2*p+1]);
    }
  }
  #pragma unroll
  for (int p = 0; p < 4; p++){
    float x0, x1, y0, y1;
    unpack2(acc[2*p],   x0, x1);
    unpack2(acc[2*p+1], y0, y1);
    *(float4*)(h2 + lane*16 + 4*p) =
        make_float4(fmaxf(x0,0.f), fmaxf(x1,0.f), fmaxf(y0,0.f), fmaxf(y1,0.f));
    unpack2(acc[8+2*p],   x0, x1);
    unpack2(acc[8+2*p+1], y0, y1);
    *(float4*)(h2 + (lane+32)*16 + 4*p) =
        make_float4(fmaxf(x0,0.f), fmaxf(x1,0.f), fmaxf(y0,0.f), fmaxf(y1,0.f));
  }
  __syncwarp();

  // ---- layer 3: h3 = W3 @ h2, fused max over neighbors ----
  #pragma unroll
  for (int p = 0; p < 16; p++) acc[p] = 0ull;
  #pragma unroll 2
  for (int j = 0; j < CC; j++){
    float wva = w3T[j*64 + lane];
    float wvb = w3T[j*64 + 32 + lane];
    unsigned long long wa = pack2(wva, wva);
    unsigned long long wb = pack2(wvb, wvb);
    const ulonglong2* hp = reinterpret_cast<const ulonglong2*>(h2 + j*16);
    #pragma unroll
    for (int p = 0; p < 4; p++){
      ulonglong2 hv = hp[p];
      acc[2*p]       = ffma2(wa, hv.x, acc[2*p]);
      acc[2*p+1]     = ffma2(wa, hv.y, acc[2*p+1]);
      acc[8 + 2*p]   = ffma2(wb, hv.x, acc[8 + 2*p]);
      acc[8 + 2*p+1] = ffma2(wb, hv.y, acc[8 + 2*p+1]);
    }
  }
  float m0 = -3.4e38f, m1 = -3.4e38f;
  #pragma unroll
  for (int p = 0; p < 8; p++){
    float lo, hi;
    unpack2(acc[p], lo, hi);       m0 = fmaxf(m0, fmaxf(lo, hi));
    unpack2(acc[8+p], lo, hi);     m1 = fmaxf(m1, fmaxf(lo, hi));
  }
  out[((size_t)b*CC + lane)      * NN + n] = m0;
  out[((size_t)b*CC + lane + 32) * NN + n] = m1;
}

// ============================================================================
extern "C" void kernel_launch(void* const* d_in, const int* in_sizes, int n_in,
                              void* d_out, int out_size)
{
  const float* xyz = (const float*)d_in[0];
  const float* w1  = (const float*)d_in[1];
  const float* w2  = (const float*)d_in[2];
  const float* w3  = (const float*)d_in[3];
  float* out = (float*)d_out;
  (void)in_sizes; (void)n_in; (void)out_size;

  knn_partial<<<dim3(NN/QB, SS, BB), QB>>>(xyz);
  knn_merge<<<(BB*NN)/MB, MB>>>();

  size_t smem = (size_t)(192 + 4096 + 4096 + WPB*2048) * sizeof(float); // 99072 B
  cudaFuncSetAttribute(mlp_kernel, cudaFuncAttributeMaxDynamicSharedMemorySize, (int)smem);
  mlp_kernel<<<(BB*NN)/WPB, TPB, smem>>>(xyz, w1, w2, w3, out);
}

// round 3
// speedup vs baseline: 1.0005x; 1.0005x over previous
#include <cuda_runtime.h>
#include <cstdint>
#include <cstddef>

#define BB 4
#define NN 4096
#define CC 64
#define KK 16
#define SS 2
#define SEG (NN/SS)      // 2048 db points per segment
#define QB 256           // queries per knn block
#define MB 128           // merge block size
#define WPB 8            // warps per mlp block
#define TPB (WPB*32)

// scratch (static device globals: no allocation allowed)
__device__ float g_cand_d[BB*NN*SS*KK];
__device__ int   g_cand_i[BB*NN*SS*KK];
__device__ int   g_knn[BB*NN*KK];

// ---- packed f32x2 helpers (FFMA2: only reachable via PTX fma.rn.f32x2) ----
__device__ __forceinline__ unsigned long long pack2(float lo, float hi){
  unsigned long long v;
  asm("mov.b64 %0, {%1,%2};" : "=l"(v) : "f"(lo), "f"(hi));
  return v;
}
__device__ __forceinline__ void unpack2(unsigned long long v, float &lo, float &hi){
  asm("mov.b64 {%0,%1}, %2;" : "=f"(lo), "=f"(hi) : "l"(v));
}
__device__ __forceinline__ unsigned long long ffma2(unsigned long long a,
                                                    unsigned long long b,
                                                    unsigned long long c){
  unsigned long long d;
  asm("fma.rn.f32x2 %0, %1, %2, %3;" : "=l"(d) : "l"(a), "l"(b), "l"(c));
  return d;
}

// ============================================================================
// Kernel 1: per-segment top-16 (register-resident, replace-by-value scheme)
// grid (NN/QB, SS, BB), block QB. Each thread owns one query, scans one
// 2048-point segment held in shared memory (SoA, broadcast reads).
// ============================================================================
__global__ __launch_bounds__(QB) void knn_partial(const float* __restrict__ xyz){
  __shared__ float sx[SEG], sy[SEG], sz[SEG];
  const int b = blockIdx.z, s = blockIdx.y;
  const float* base = xyz + (size_t)b * NN * 3;
  const int jg0 = s * SEG;
  for (int i = threadIdx.x; i < SEG; i += QB){
    int j = jg0 + i;
    sx[i] = base[j*3+0]; sy[i] = base[j*3+1]; sz[i] = base[j*3+2];
  }
  __syncthreads();

  const int q = blockIdx.x * QB + threadIdx.x;
  const float qx = base[q*3+0], qy = base[q*3+1], qz = base[q*3+2];

  // distinct huge sentinels so "replace entry equal to worst" hits exactly one
  float bd[KK]; int bi[KK];
  #pragma unroll
  for (int i = 0; i < KK; i++){
    bd[i] = __uint_as_float(0x7F000000u - (unsigned)i);
    bi[i] = 0;
  }
  float worst = __uint_as_float(0x7F000000u);

  #pragma unroll 4
  for (int j = 0; j < SEG; j++){
    float dx = qx - sx[j], dy = qy - sy[j], dz = qz - sz[j];
    float d = dx*dx;
    d = fmaf(dy, dy, d);
    d = fmaf(dz, dz, d);
    int jg = jg0 + j;
    if (d < worst && jg != q){
      #pragma unroll
      for (int i = 0; i < KK; i++){
        if (bd[i] == worst){ bd[i] = d; bi[i] = jg; }
      }
      // recompute worst via fmax tree (parallel, depth 4)
      float t0 = fmaxf(bd[0],  bd[1]),  t1 = fmaxf(bd[2],  bd[3]);
      float t2 = fmaxf(bd[4],  bd[5]),  t3 = fmaxf(bd[6],  bd[7]);
      float t4 = fmaxf(bd[8],  bd[9]),  t5 = fmaxf(bd[10], bd[11]);
      float t6 = fmaxf(bd[12], bd[13]), t7 = fmaxf(bd[14], bd[15]);
      t0 = fmaxf(t0, t1); t2 = fmaxf(t2, t3);
      t4 = fmaxf(t4, t5); t6 = fmaxf(t6, t7);
      worst = fmaxf(fmaxf(t0, t2), fmaxf(t4, t6));
    }
  }

  size_t o = (((size_t)b * NN + q) * SS + s) * KK;
  #pragma unroll
  for (int i = 0; i < KK; i++){ g_cand_d[o+i] = bd[i]; g_cand_i[o+i] = bi[i]; }
}

// ============================================================================
// Kernel 2: merge SS*16 candidates per query -> final 16 (unordered is fine:
// downstream is max-pool; ascending scan keeps lower index on exact ties,
// matching jax top_k tie-breaking)
// ============================================================================
__global__ __launch_bounds__(MB) void knn_merge(){
  __shared__ float sd[MB][SS*KK + 1];   // +1 pad kills bank conflicts
  __shared__ int   si[MB][SS*KK + 1];
  const int t = threadIdx.x;
  const int g = blockIdx.x * MB + t;    // global point id (b*NN+n)
  size_t o = (size_t)g * SS * KK;
  #pragma unroll
  for (int i = 0; i < SS*KK; i++){ sd[t][i] = g_cand_d[o+i]; si[t][i] = g_cand_i[o+i]; }

  const int outbase = g * KK;
  for (int r = 0; r < KK; r++){
    float best = 3.0e38f; int bp = 0;
    #pragma unroll
    for (int i = 0; i < SS*KK; i++){
      float v = sd[t][i];
      if (v < best){ best = v; bp = i; }
    }
    g_knn[outbase + r] = si[t][bp];
    sd[t][bp] = 3.2e38f;   // mark used
  }
}

// ============================================================================
// Kernel 3: fused rel-coords + 3-layer MLP + neighbor max-pool.
// One warp per point. Lane l owns output channels l and l+32.
// h tiles in shared as [c][nb] (16 floats/row) so neighbor pairs load as
// broadcast ld.shared.v2.b64 feeding packed fma.rn.f32x2 accumulators.
// ============================================================================
__global__ __launch_bounds__(TPB) void mlp_kernel(
    const float* __restrict__ xyz,
    const float* __restrict__ w1,
    const float* __restrict__ w2,
    const float* __restrict__ w3,
    float* __restrict__ out)
{
  extern __shared__ float sm[];
  float* w1s = sm;             // 192
  float* w2T = sm + 192;       // 4096  (w2T[c_in*64 + c_out])
  float* w3T = w2T + 4096;     // 4096
  float* hb  = w3T + 4096;     // WPB * 2048

  const int tid = threadIdx.x, wid = tid >> 5, lane = tid & 31;

  for (int t = tid; t < 192; t += TPB) w1s[t] = w1[t];
  for (int t = tid; t < 4096; t += TPB){
    int o = t >> 6, c = t & 63;
    w2T[c*64 + o] = w2[t];
    w3T[c*64 + o] = w3[t];
  }
  __syncthreads();

  const int point = blockIdx.x * WPB + wid;       // 0..BB*NN-1
  const int b = point >> 12;
  const int n = point & (NN - 1);
  const float* base = xyz + (size_t)b * NN * 3;

  float* h1 = hb + wid * 2048;
  float* h2 = h1 + 1024;

  const float cx = base[n*3+0], cy = base[n*3+1], cz = base[n*3+2];

  // stage relative coords in h2[0..47] (free until layer-2 writes)
  if (lane < KK){
    int ng = g_knn[point*KK + lane];
    h2[lane]      = base[ng*3+0] - cx;
    h2[16 + lane] = base[ng*3+1] - cy;
    h2[32 + lane] = base[ng*3+2] - cz;
  }
  __syncwarp();

  // ---- layer 1: h1[c][nb] = relu(w1[c] . rel[nb]) ----
  {
    const int c0 = lane, c1 = lane + 32;
    const float a0 = w1s[c0*3], b0 = w1s[c0*3+1], g0 = w1s[c0*3+2];
    const float a1 = w1s[c1*3], b1 = w1s[c1*3+1], g1 = w1s[c1*3+2];
    #pragma unroll
    for (int nb = 0; nb < KK; nb += 4){
      float o0[4], o1[4];
      #pragma unroll
      for (int u = 0; u < 4; u++){
        float rx = h2[nb+u], ry = h2[16+nb+u], rz = h2[32+nb+u];
        o0[u] = fmaxf(fmaf(a0, rx, fmaf(b0, ry, g0*rz)), 0.f);
        o1[u] = fmaxf(fmaf(a1, rx, fmaf(b1, ry, g1*rz)), 0.f);
      }
      *(float4*)(h1 + c0*16 + nb) = make_float4(o0[0], o0[1], o0[2], o0[3]);
      *(float4*)(h1 + c1*16 + nb) = make_float4(o1[0], o1[1], o1[2], o1[3]);
    }
  }
  __syncwarp();

  unsigned long long acc[16];

  // ---- layer 2: h2 = relu(W2 @ h1) ----
  #pragma unroll
  for (int p = 0; p < 16; p++) acc[p] = 0ull;
  #pragma unroll 2
  for (int j = 0; j < CC; j++){
    float wva = w2T[j*64 + lane];
    float wvb = w2T[j*64 + 32 + lane];
    unsigned long long wa = pack2(wva, wva);
    unsigned long long wb = pack2(wvb, wvb);
    const ulonglong2* hp = reinterpret_cast<const ulonglong2*>(h1 + j*16);
    #pragma unroll
    for (int p = 0; p < 4; p++){
      ulonglong2 hv = hp[p];
      acc[2*p]       = ffma2(wa, hv.x, acc[2*p]);
      acc[2*p+1]     = ffma2(wa, hv.y, acc[2*p+1]);
      acc[8 + 2*p]   = ffma2(wb, hv.x, acc[8 + 2*p]);
      acc[8 + 2*p+1] = ffma2(wb, hv.y, acc[8 + 2*p+1]);
    }
  }
  #pragma unroll
  for (int p = 0; p < 4; p++){
    float x0, x1, y0, y1;
    unpack2(acc[2*p],   x0, x1);
    unpack2(acc[2*p+1], y0, y1);
    *(float4*)(h2 + lane*16 + 4*p) =
        make_float4(fmaxf(x0,0.f), fmaxf(x1,0.f), fmaxf(y0,0.f), fmaxf(y1,0.f));
    unpack2(acc[8+2*p],   x0, x1);
    unpack2(acc[8+2*p+1], y0, y1);
    *(float4*)(h2 + (lane+32)*16 + 4*p) =
        make_float4(fmaxf(x0,0.f), fmaxf(x1,0.f), fmaxf(y0,0.f), fmaxf(y1,0.f));
  }
  __syncwarp();

  // ---- layer 3: h3 = W3 @ h2, fused max over neighbors ----
  #pragma unroll
  for (int p = 0; p < 16; p++) acc[p] = 0ull;
  #pragma unroll 2
  for (int j = 0; j < CC; j++){
    float wva = w3T[j*64 + lane];
    float wvb = w3T[j*64 + 32 + lane];
    unsigned long long wa = pack2(wva, wva);
    unsigned long long wb = pack2(wvb, wvb);
    const ulonglong2* hp = reinterpret_cast<const ulonglong2*>(h2 + j*16);
    #pragma unroll
    for (int p = 0; p < 4; p++){
      ulonglong2 hv = hp[p];
      acc[2*p]       = ffma2(wa, hv.x, acc[2*p]);
      acc[2*p+1]     = ffma2(wa, hv.y, acc[2*p+1]);
      acc[8 + 2*p]   = ffma2(wb, hv.x, acc[8 + 2*p]);
      acc[8 + 2*p+1] = ffma2(wb, hv.y, acc[8 + 2*p+1]);
    }
  }
  float m0 = -3.4e38f, m1 = -3.4e38f;
  #pragma unroll
  for (int p = 0; p < 8; p++){
    float lo, hi;
    unpack2(acc[p], lo, hi);       m0 = fmaxf(m0, fmaxf(lo, hi));
    unpack2(acc[8+p], lo, hi);     m1 = fmaxf(m1, fmaxf(lo, hi));
  }
  out[((size_t)b*CC + lane)      * NN + n] = m0;
  out[((size_t)b*CC + lane + 32) * NN + n] = m1;
}

// ============================================================================
extern "C" void kernel_launch(void* const* d_in, const int* in_sizes, int n_in,
                              void* d_out, int out_size)
{
  const float* xyz = (const float*)d_in[0];
  const float* w1  = (const float*)d_in[1];
  const float* w2  = (const float*)d_in[2];
  const float* w3  = (const float*)d_in[3];
  float* out = (float*)d_out;
  (void)in_sizes; (void)n_in; (void)out_size;

  knn_partial<<<dim3(NN/QB, SS, BB), QB>>>(xyz);
  knn_merge<<<(BB*NN)/MB, MB>>>();

  size_t smem = (size_t)(192 + 4096 + 4096 + WPB*2048) * sizeof(float); // 99072 B
  cudaFuncSetAttribute(mlp_kernel, cudaFuncAttributeMaxDynamicSharedMemorySize, (int)smem);
  mlp_kernel<<<(BB*NN)/WPB, TPB, smem>>>(xyz, w1, w2, w3, out);
}

// round 4
// speedup vs baseline: 1.3407x; 1.3400x over previous
#include <cuda_runtime.h>
#include <cstdint>
#include <cstddef>
#include <math_constants.h>

#define BB 4
#define NN 4096
#define CC 64
#define KK 16
#define QW 16            // query-warps per knn block
#define WPB 8            // warps per mlp block
#define TPB (WPB*32)

// scratch (static device globals: no allocation allowed)
__device__ int g_knn[BB*NN*KK];

// ---- packed f32x2 helpers (FFMA2: only reachable via PTX fma.rn.f32x2) ----
__device__ __forceinline__ unsigned long long pack2(float lo, float hi){
  unsigned long long v;
  asm("mov.b64 %0, {%1,%2};" : "=l"(v) : "f"(lo), "f"(hi));
  return v;
}
__device__ __forceinline__ void unpack2(unsigned long long v, float &lo, float &hi){
  asm("mov.b64 {%0,%1}, %2;" : "=f"(lo), "=f"(hi) : "l"(v));
}
__device__ __forceinline__ unsigned long long ffma2(unsigned long long a,
                                                    unsigned long long b,
                                                    unsigned long long c){
  unsigned long long d;
  asm("fma.rn.f32x2 %0, %1, %2, %3;" : "=l"(d) : "l"(a), "l"(b), "l"(c));
  return d;
}

// ============================================================================
// Kernel 1: warp-per-query exact 16-NN, distributed top-16 + warp-shared
// threshold. Lanes 0..15 each own one of the current best-16 (dist,idx).
// Hot loop: 32 candidate distances/iteration, ballot; inserts are rare
// (~105/query total) and handled serially per set bit with threshold recheck.
// ============================================================================
__global__ __launch_bounds__(QW*32) void knn_warp(const float* __restrict__ xyz){
  __shared__ float s[NN*3];          // 48KB: flat [j*3 + c], stride-3 = conflict-free
  const int b = blockIdx.y;
  const float* base = xyz + (size_t)b * NN * 3;
  const int tid = threadIdx.x;
  for (int i = tid; i < NN*3; i += QW*32) s[i] = base[i];
  __syncthreads();

  const int wid = tid >> 5, lane = tid & 31;
  const int q = blockIdx.x * QW + wid;
  const float qx = s[3*q], qy = s[3*q+1], qz = s[3*q+2];

  // warm-start: lanes 0..15 seeded with points 0..15 (self -> +inf)
  float myD = CUDART_INF_F; int myIdx = 0;
  if (lane < KK){
    int j = lane;
    float dx = qx - s[3*j], dy = qy - s[3*j+1], dz = qz - s[3*j+2];
    float d = fmaf(dx, dx, fmaf(dy, dy, dz*dz));
    myD = (j == q) ? CUDART_INF_F : d;
    myIdx = j;
  }
  float w = (lane < KK) ? myD : -CUDART_INF_F;
  #pragma unroll
  for (int x = 16; x; x >>= 1) w = fmaxf(w, __shfl_xor_sync(0xffffffffu, w, x));
  float worst = w;

  for (int j0 = KK; j0 < NN; j0 += 32){
    int j = j0 + lane;
    int jc = (j < NN) ? j : (NN - 1);
    float dx = qx - s[3*jc], dy = qy - s[3*jc+1], dz = qz - s[3*jc+2];
    float d = fmaf(dx, dx, fmaf(dy, dy, dz*dz));
    bool hit = (d < worst) && (j != q) && (j < NN);
    unsigned m = __ballot_sync(0xffffffffu, hit);
    while (m){
      int src = __ffs(m) - 1; m &= m - 1;
      float cd = __shfl_sync(0xffffffffu, d, src);
      if (cd < worst){                       // warp-uniform recheck
        unsigned em = __ballot_sync(0xffffffffu, (lane < KK) && (myD == worst));
        int leader = __ffs(em) - 1;
        if (lane == leader){ myD = cd; myIdx = j0 + src; }
        float v = (lane < KK) ? myD : -CUDART_INF_F;
        #pragma unroll
        for (int x = 16; x; x >>= 1) v = fmaxf(v, __shfl_xor_sync(0xffffffffu, v, x));
        worst = v;
      }
    }
  }
  if (lane < KK) g_knn[((size_t)b * NN + q) * KK + lane] = myIdx;
}

// ============================================================================
// Kernel 2: fused rel-coords + 3-layer MLP + neighbor max-pool (unchanged).
// One warp per point. Lane l owns output channels l and l+32.
// ============================================================================
__global__ __launch_bounds__(TPB) void mlp_kernel(
    const float* __restrict__ xyz,
    const float* __restrict__ w1,
    const float* __restrict__ w2,
    const float* __restrict__ w3,
    float* __restrict__ out)
{
  extern __shared__ float sm[];
  float* w1s = sm;             // 192
  float* w2T = sm + 192;       // 4096  (w2T[c_in*64 + c_out])
  float* w3T = w2T + 4096;     // 4096
  float* hb  = w3T + 4096;     // WPB * 2048

  const int tid = threadIdx.x, wid = tid >> 5, lane = tid & 31;

  for (int t = tid; t < 192; t += TPB) w1s[t] = w1[t];
  for (int t = tid; t < 4096; t += TPB){
    int o = t >> 6, c = t & 63;
    w2T[c*64 + o] = w2[t];
    w3T[c*64 + o] = w3[t];
  }
  __syncthreads();

  const int point = blockIdx.x * WPB + wid;       // 0..BB*NN-1
  const int b = point >> 12;
  const int n = point & (NN - 1);
  const float* base = xyz + (size_t)b * NN * 3;

  float* h1 = hb + wid * 2048;
  float* h2 = h1 + 1024;

  const float cx = base[n*3+0], cy = base[n*3+1], cz = base[n*3+2];

  if (lane < KK){
    int ng = g_knn[point*KK + lane];
    h2[lane]      = base[ng*3+0] - cx;
    h2[16 + lane] = base[ng*3+1] - cy;
    h2[32 + lane] = base[ng*3+2] - cz;
  }
  __syncwarp();

  // ---- layer 1 ----
  {
    const int c0 = lane, c1 = lane + 32;
    const float a0 = w1s[c0*3], b0 = w1s[c0*3+1], g0 = w1s[c0*3+2];
    const float a1 = w1s[c1*3], b1 = w1s[c1*3+1], g1 = w1s[c1*3+2];
    #pragma unroll
    for (int nb = 0; nb < KK; nb += 4){
      float o0[4], o1[4];
      #pragma unroll
      for (int u = 0; u < 4; u++){
        float rx = h2[nb+u], ry = h2[16+nb+u], rz = h2[32+nb+u];
        o0[u] = fmaxf(fmaf(a0, rx, fmaf(b0, ry, g0*rz)), 0.f);
        o1[u] = fmaxf(fmaf(a1, rx, fmaf(b1, ry, g1*rz)), 0.f);
      }
      *(float4*)(h1 + c0*16 + nb) = make_float4(o0[0], o0[1], o0[2], o0[3]);
      *(float4*)(h1 + c1*16 + nb) = make_float4(o1[0], o1[1], o1[2], o1[3]);
    }
  }
  __syncwarp();

  unsigned long long acc[16];

  // ---- layer 2 ----
  #pragma unroll
  for (int p = 0; p < 16; p++) acc[p] = 0ull;
  #pragma unroll 2
  for (int j = 0; j < CC; j++){
    float wva = w2T[j*64 + lane];
    float wvb = w2T[j*64 + 32 + lane];
    unsigned long long wa = pack2(wva, wva);
    unsigned long long wb = pack2(wvb, wvb);
    const ulonglong2* hp = reinterpret_cast<const ulonglong2*>(h1 + j*16);
    #pragma unroll
    for (int p = 0; p < 4; p++){
      ulonglong2 hv = hp[p];
      acc[2*p]       = ffma2(wa, hv.x, acc[2*p]);
      acc[2*p+1]     = ffma2(wa, hv.y, acc[2*p+1]);
      acc[8 + 2*p]   = ffma2(wb, hv.x, acc[8 + 2*p]);
      acc[8 + 2*p+1] = ffma2(wb, hv.y, acc[8 + 2*p+1]);
    }
  }
  #pragma unroll
  for (int p = 0; p < 4; p++){
    float x0, x1, y0, y1;
    unpack2(acc[2*p],   x0, x1);
    unpack2(acc[2*p+1], y0, y1);
    *(float4*)(h2 + lane*16 + 4*p) =
        make_float4(fmaxf(x0,0.f), fmaxf(x1,0.f), fmaxf(y0,0.f), fmaxf(y1,0.f));
    unpack2(acc[8+2*p],   x0, x1);
    unpack2(acc[8+2*p+1], y0, y1);
    *(float4*)(h2 + (lane+32)*16 + 4*p) =
        make_float4(fmaxf(x0,0.f), fmaxf(x1,0.f), fmaxf(y0,0.f), fmaxf(y1,0.f));
  }
  __syncwarp();

  // ---- layer 3 + fused max-pool ----
  #pragma unroll
  for (int p = 0; p < 16; p++) acc[p] = 0ull;
  #pragma unroll 2
  for (int j = 0; j < CC; j++){
    float wva = w3T[j*64 + lane];
    float wvb = w3T[j*64 + 32 + lane];
    unsigned long long wa = pack2(wva, wva);
    unsigned long long wb = pack2(wvb, wvb);
    const ulonglong2* hp = reinterpret_cast<const ulonglong2*>(h2 + j*16);
    #pragma unroll
    for (int p = 0; p < 4; p++){
      ulonglong2 hv = hp[p];
      acc[2*p]       = ffma2(wa, hv.x, acc[2*p]);
      acc[2*p+1]     = ffma2(wa, hv.y, acc[2*p+1]);
      acc[8 + 2*p]   = ffma2(wb, hv.x, acc[8 + 2*p]);
      acc[8 + 2*p+1] = ffma2(wb, hv.y, acc[8 + 2*p+1]);
    }
  }
  float m0 = -3.4e38f, m1 = -3.4e38f;
  #pragma unroll
  for (int p = 0; p < 8; p++){
    float lo, hi;
    unpack2(acc[p], lo, hi);       m0 = fmaxf(m0, fmaxf(lo, hi));
    unpack2(acc[8+p], lo, hi);     m1 = fmaxf(m1, fmaxf(lo, hi));
  }
  out[((size_t)b*CC + lane)      * NN + n] = m0;
  out[((size_t)b*CC + lane + 32) * NN + n] = m1;
}

// ============================================================================
extern "C" void kernel_launch(void* const* d_in, const int* in_sizes, int n_in,
                              void* d_out, int out_size)
{
  const float* xyz = (const float*)d_in[0];
  const float* w1  = (const float*)d_in[1];
  const float* w2  = (const float*)d_in[2];
  const float* w3  = (const float*)d_in[3];
  float* out = (float*)d_out;
  (void)in_sizes; (void)n_in; (void)out_size;

  knn_warp<<<dim3(NN/QW, BB), QW*32>>>(xyz);

  size_t smem = (size_t)(192 + 4096 + 4096 + WPB*2048) * sizeof(float); // 99072 B
  cudaFuncSetAttribute(mlp_kernel, cudaFuncAttributeMaxDynamicSharedMemorySize, (int)smem);
  mlp_kernel<<<(BB*NN)/WPB, TPB, smem>>>(xyz, w1, w2, w3, out);
}